// round 5
// baseline (speedup 1.0000x reference)
#include <cuda_runtime.h>
#include <math.h>

#define B_  8
#define T_  4096
#define H_  4
#define HV_ 8
#define K_  128
#define V_  128
#define REP_ (HV_/H_)   // 2

// Scratch (static __device__ arrays: allocation-free per harness rules)
__device__ float  g_qn[(size_t)B_*T_*H_*K_];   // l2-normalized q * K^-0.5
__device__ float  g_kn[(size_t)B_*T_*H_*K_];   // l2-normalized k
__device__ float  g_kq[(size_t)B_*T_*H_];      // (qn . kn) per row
__device__ float2 g_gb[(size_t)B_*T_*HV_];     // {exp(g), sigmoid(b)}

// ---------------------------------------------------------------------------
// f32x2 packed helpers (sm_103a FFMA2 path — PTX only, ptxas won't auto-fuse)
// ---------------------------------------------------------------------------
typedef unsigned long long u64t;
__device__ __forceinline__ u64t pk2(float lo, float hi) {
    u64t r; asm("mov.b64 %0,{%1,%2};" : "=l"(r) : "f"(lo), "f"(hi)); return r;
}
__device__ __forceinline__ void up2(u64t p, float& lo, float& hi) {
    asm("mov.b64 {%0,%1},%2;" : "=f"(lo), "=f"(hi) : "l"(p));
}
__device__ __forceinline__ u64t fma2(u64t a, u64t b, u64t c) {
    u64t d; asm("fma.rn.f32x2 %0,%1,%2,%3;" : "=l"(d) : "l"(a), "l"(b), "l"(c)); return d;
}
__device__ __forceinline__ u64t mul2(u64t a, u64t b) {
    u64t d; asm("mul.rn.f32x2 %0,%1,%2;" : "=l"(d) : "l"(a), "l"(b)); return d;
}

// ---------------------------------------------------------------------------
// Prepass 1: per (b,t,h) row — l2norm q and k over K=128, fold scale into q,
// and precompute kq = qn . kn (used for the output shortcut in the scan).
// 4 warps per block, one row per warp.
// ---------------------------------------------------------------------------
__global__ void __launch_bounds__(128) prep_qk(const float* __restrict__ q,
                                               const float* __restrict__ k) {
    int warp = threadIdx.x >> 5;
    int lane = threadIdx.x & 31;
    size_t row = (size_t)blockIdx.x * 4 + warp;
    const float4* q4 = reinterpret_cast<const float4*>(q + row * K_);
    const float4* k4 = reinterpret_cast<const float4*>(k + row * K_);
    float4 qa = q4[lane];
    float4 ka = k4[lane];
    float sq = qa.x*qa.x + qa.y*qa.y + qa.z*qa.z + qa.w*qa.w;
    float sk = ka.x*ka.x + ka.y*ka.y + ka.z*ka.z + ka.w*ka.w;
    float dp = qa.x*ka.x + qa.y*ka.y + qa.z*ka.z + qa.w*ka.w;
    #pragma unroll
    for (int o = 16; o > 0; o >>= 1) {
        sq += __shfl_xor_sync(0xffffffffu, sq, o);
        sk += __shfl_xor_sync(0xffffffffu, sk, o);
        dp += __shfl_xor_sync(0xffffffffu, dp, o);
    }
    const float scale = 0.088388347648318440550f;   // 128^-0.5
    float iq = rsqrtf(sq + 1e-6f) * scale;
    float ik = rsqrtf(sk + 1e-6f);
    float4 qo = make_float4(qa.x*iq, qa.y*iq, qa.z*iq, qa.w*iq);
    float4 ko = make_float4(ka.x*ik, ka.y*ik, ka.z*ik, ka.w*ik);
    reinterpret_cast<float4*>(g_qn + row * K_)[lane] = qo;
    reinterpret_cast<float4*>(g_kn + row * K_)[lane] = ko;
    if (lane == 0) g_kq[row] = dp * iq * ik;
}

// ---------------------------------------------------------------------------
// Prepass 2: per (b,t,hv) — eg = exp(-exp(A_log)*softplus(a+dt_bias)),
// beta = sigmoid(b). Packed as float2 so the scan does one LDG.64.
// ---------------------------------------------------------------------------
__global__ void __launch_bounds__(256) prep_gate(const float* __restrict__ A_log,
                                                 const float* __restrict__ a,
                                                 const float* __restrict__ dt_bias,
                                                 const float* __restrict__ b) {
    size_t i = (size_t)blockIdx.x * blockDim.x + threadIdx.x;
    if (i >= (size_t)B_*T_*HV_) return;
    int hv = (int)(i % HV_);
    float x = a[i] + dt_bias[hv];
    float sp = (x <= 20.0f) ? log1pf(expf(x)) : x;   // softplus, beta=1, thr=20
    float g  = -expf(A_log[hv]) * sp;
    float bt = 1.0f / (1.0f + expf(-b[i]));
    g_gb[i] = make_float2(expf(g), bt);
}

// ---------------------------------------------------------------------------
// Main persistent recurrence.
// grid = B*HV*2 = 128 CTAs, 256 threads (8 warps/CTA -> 2 warps/SMSP).
//   blockIdx.x: bit0 = v-half, bits[1:3] = hv, bits[4:6] = b
//   thread: kh = tid&3 (K quarter, 32 floats), col = tid>>2 (local V column)
// Each thread holds 32 state floats as 16 packed f32x2 regs.
// Per step:
//   pass1: hk = h.k_quarter, hq = h.q_quarter   (32 fma2, two parallel dots)
//   shfl_xor(1),(2): reduce over the 4 K-quarters
//   u = (v - eg*hk)*beta ;  o = eg*hq + u*kq   (kq precomputed over full K)
//   pass2: h = eg*h + u*k                       (16 mul2 + 16 fma2)
// No __syncthreads, no MUFU, no spills in the T loop.
// ---------------------------------------------------------------------------
__global__ void __launch_bounds__(256, 1) gdn_recurrent(
    const float* __restrict__ vin,
    const float* __restrict__ h0src,
    const int*   __restrict__ h0idx,
    float* __restrict__ out)
{
    int blk   = blockIdx.x;
    int vhalf = blk & 1;
    int hv    = (blk >> 1) & (HV_ - 1);
    int b     = blk >> 4;
    int tid   = threadIdx.x;
    int kh    = tid & 3;
    int col   = tid >> 2;
    int v     = vhalf * 64 + col;
    int hh    = hv / REP_;

    // State: k indices [kh*32, kh*32+32), packed pairs (2i, 2i+1)
    u64t h2[16];
    int idx = h0idx[b];
    if (idx >= 0) {
        const float* src = h0src + (((size_t)idx * HV_ + hv) * K_ + (size_t)kh * 32) * V_ + v;
        #pragma unroll
        for (int i = 0; i < 16; i++)
            h2[i] = pk2(src[(size_t)(2*i) * V_], src[(size_t)(2*i+1) * V_]);
    } else {
        #pragma unroll
        for (int i = 0; i < 16; i++) h2[i] = 0ull;
    }

    const float*  knb = g_kn + ((size_t)b * T_ * H_ + hh) * K_ + (size_t)kh * 32;
    const float*  qnb = g_qn + ((size_t)b * T_ * H_ + hh) * K_ + (size_t)kh * 32;
    const float*  kqp = g_kq + (size_t)b * T_ * H_ + hh;
    const float2* gbp = g_gb + (size_t)b * T_ * HV_ + hv;
    const float*  vp  = vin  + ((size_t)b * T_ * HV_ + hv) * V_ + v;
    float*        op  = out  + ((size_t)b * T_ * HV_ + hv) * V_ + v;

    for (int t = 0; t < T_; t++) {
        float2 gb = gbp[0];
        float  eg = gb.x, beta = gb.y;
        float  vt = vp[0];
        float  kq = kqp[0];

        // Pass 1: two dot products against h_old, fully parallel (4 chains of 8)
        const float4* k4 = reinterpret_cast<const float4*>(knb);
        const float4* q4 = reinterpret_cast<const float4*>(qnb);
        u64t k2[16];
        u64t hkA = 0ull, hkB = 0ull, hqA = 0ull, hqB = 0ull;
        #pragma unroll
        for (int j = 0; j < 8; j++) {
            float4 kv = k4[j];
            float4 qv = q4[j];
            k2[2*j]   = pk2(kv.x, kv.y);
            k2[2*j+1] = pk2(kv.z, kv.w);
            u64t qlo  = pk2(qv.x, qv.y);
            u64t qhi  = pk2(qv.z, qv.w);
            hkA = fma2(h2[2*j],   k2[2*j],   hkA);
            hkB = fma2(h2[2*j+1], k2[2*j+1], hkB);
            hqA = fma2(h2[2*j],   qlo,       hqA);
            hqB = fma2(h2[2*j+1], qhi,       hqB);
        }
        float a0, a1, b0, b1;
        up2(hkA, a0, a1); up2(hkB, b0, b1);
        float hk = (a0 + a1) + (b0 + b1);
        up2(hqA, a0, a1); up2(hqB, b0, b1);
        float hq = (a0 + a1) + (b0 + b1);

        // Reduce over the 4 K-quarters (lanes l, l^1, l^2, l^3 share this v)
        hk += __shfl_xor_sync(0xffffffffu, hk, 1);
        hq += __shfl_xor_sync(0xffffffffu, hq, 1);
        hk += __shfl_xor_sync(0xffffffffu, hk, 2);
        hq += __shfl_xor_sync(0xffffffffu, hq, 2);

        float u = fmaf(-eg, hk, vt) * beta;          // (v - eg*(h.k)) * beta
        float o = fmaf(eg, hq, u * kq);              // eg*(h.q) + u*(k.q)
        if (kh == 0) *op = o;

        // Pass 2: h = eg*h + u*k  (16 independent mul2->fma2 chains)
        u64t eg2 = pk2(eg, eg);
        u64t u2  = pk2(u, u);
        #pragma unroll
        for (int i = 0; i < 16; i++)
            h2[i] = fma2(k2[i], u2, mul2(h2[i], eg2));

        knb += H_ * K_;
        qnb += H_ * K_;
        kqp += H_;
        gbp += HV_;
        vp  += HV_ * V_;
        op  += HV_ * V_;
    }
}

// ---------------------------------------------------------------------------
// Inputs (metadata order): A_log, a, dt_bias, q, k, v, b,
//                          initial_state_source, initial_state_indices
// Output: float32 [B,T,HV,V]
// ---------------------------------------------------------------------------
extern "C" void kernel_launch(void* const* d_in, const int* in_sizes, int n_in,
                              void* d_out, int out_size) {
    const float* A_log = (const float*)d_in[0];
    const float* a     = (const float*)d_in[1];
    const float* dtb   = (const float*)d_in[2];
    const float* q     = (const float*)d_in[3];
    const float* k     = (const float*)d_in[4];
    const float* v     = (const float*)d_in[5];
    const float* bb    = (const float*)d_in[6];
    const float* h0    = (const float*)d_in[7];
    const int*   h0i   = (const int*)d_in[8];
    float* out = (float*)d_out;

    prep_qk<<<(B_ * T_ * H_) / 4, 128>>>(q, k);
    prep_gate<<<((size_t)B_ * T_ * HV_ + 255) / 256, 256>>>(A_log, a, dtb, bb);
    gdn_recurrent<<<B_ * HV_ * 2, 256>>>(v, h0, h0i, out);
}

// round 6
// speedup vs baseline: 1.6073x; 1.6073x over previous
#include <cuda_runtime.h>
#include <math.h>

#define B_  8
#define T_  4096
#define H_  4
#define HV_ 8
#define K_  128
#define V_  128
#define REP_ (HV_/H_)   // 2

// Scratch (static __device__ arrays: allocation-free per harness rules).
// Each stream is padded by one t-row so the software prefetch of step T reads
// valid (garbage, never consumed) memory without a branch.
__device__ float  g_qn[(size_t)B_*T_*H_*K_ + H_*K_];   // l2-normalized q * K^-0.5
__device__ float  g_kn[(size_t)B_*T_*H_*K_ + H_*K_];   // l2-normalized k
__device__ float  g_kq[(size_t)B_*T_*H_   + H_];       // (qn . kn) per row
__device__ float2 g_gb[(size_t)B_*T_*HV_  + HV_];      // {exp(g), sigmoid(b)}

// ---------------------------------------------------------------------------
// Prepass 1: per (b,t,h) row — l2norm q and k over K=128, fold scale into q,
// and precompute kq = qn . kn (output shortcut for the scan).
// ---------------------------------------------------------------------------
__global__ void __launch_bounds__(128) prep_qk(const float* __restrict__ q,
                                               const float* __restrict__ k) {
    int warp = threadIdx.x >> 5;
    int lane = threadIdx.x & 31;
    size_t row = (size_t)blockIdx.x * 4 + warp;
    const float4* q4 = reinterpret_cast<const float4*>(q + row * K_);
    const float4* k4 = reinterpret_cast<const float4*>(k + row * K_);
    float4 qa = q4[lane];
    float4 ka = k4[lane];
    float sq = qa.x*qa.x + qa.y*qa.y + qa.z*qa.z + qa.w*qa.w;
    float sk = ka.x*ka.x + ka.y*ka.y + ka.z*ka.z + ka.w*ka.w;
    float dp = qa.x*ka.x + qa.y*ka.y + qa.z*ka.z + qa.w*ka.w;
    #pragma unroll
    for (int o = 16; o > 0; o >>= 1) {
        sq += __shfl_xor_sync(0xffffffffu, sq, o);
        sk += __shfl_xor_sync(0xffffffffu, sk, o);
        dp += __shfl_xor_sync(0xffffffffu, dp, o);
    }
    const float scale = 0.088388347648318440550f;   // 128^-0.5
    float iq = rsqrtf(sq + 1e-6f) * scale;
    float ik = rsqrtf(sk + 1e-6f);
    reinterpret_cast<float4*>(g_qn + row * K_)[lane] =
        make_float4(qa.x*iq, qa.y*iq, qa.z*iq, qa.w*iq);
    reinterpret_cast<float4*>(g_kn + row * K_)[lane] =
        make_float4(ka.x*ik, ka.y*ik, ka.z*ik, ka.w*ik);
    if (lane == 0) g_kq[row] = dp * iq * ik;
}

// ---------------------------------------------------------------------------
// Prepass 2: per (b,t,hv) — eg = exp(-exp(A_log)*softplus(a+dt_bias)),
// beta = sigmoid(b). Packed float2 -> one LDG.64 in the scan.
// ---------------------------------------------------------------------------
__global__ void __launch_bounds__(256) prep_gate(const float* __restrict__ A_log,
                                                 const float* __restrict__ a,
                                                 const float* __restrict__ dt_bias,
                                                 const float* __restrict__ b) {
    size_t i = (size_t)blockIdx.x * blockDim.x + threadIdx.x;
    if (i >= (size_t)B_*T_*HV_) return;
    int hv = (int)(i % HV_);
    float x = a[i] + dt_bias[hv];
    float sp = (x <= 20.0f) ? log1pf(expf(x)) : x;   // softplus, beta=1, thr=20
    float g  = -expf(A_log[hv]) * sp;
    float bt = 1.0f / (1.0f + expf(-b[i]));
    g_gb[i] = make_float2(expf(g), bt);
}

// ---------------------------------------------------------------------------
// Main persistent recurrence. grid = B*HV*2 = 128 CTAs, 256 threads
// (8 warps/CTA -> 2 warps/SMSP for latency hiding).
//   blockIdx.x: bit0 = v-half, bits[1:3] = hv, bits[4:6] = b
//   thread: kh = tid&3 (K-quarter, 32 floats), col = tid>>2 (local V column)
// Per step (scalar FFMA, software-prefetched streams):
//   prefetch k(t+1)+scalars(t+1) -> pass1 dots (h.k, h.q) -> prefetch q(t+1)
//   -> shfl reduce (xor 1,2) -> u,o scalar -> store o -> h = eg*h + u*k
// No __syncthreads, no MUFU, compile-time buffer parity (loop unrolled x2).
// ---------------------------------------------------------------------------

#define STEP(KC, KN, T1VALID)                                              \
{                                                                          \
    /* 1. prefetch k(t+1) + scalar streams (t+1) */                        \
    _Pragma("unroll")                                                      \
    for (int j = 0; j < 8; j++) KN[j] = kp[j];                             \
    float2 gb_n = gbp[0];                                                  \
    float  kq_n = kqp[0];                                                  \
    float  vt_n = (T1VALID) ? vp[0] : 0.0f;                                \
    /* 2. pass1: hk = h.k_quarter, hq = h.q_quarter (8 parallel chains) */ \
    float hk0=0.f,hk1=0.f,hk2=0.f,hk3=0.f;                                 \
    float hq0=0.f,hq1=0.f,hq2=0.f,hq3=0.f;                                 \
    _Pragma("unroll")                                                      \
    for (int j = 0; j < 8; j++) {                                          \
        hk0 = fmaf(h[4*j+0], KC[j].x, hk0);                                \
        hk1 = fmaf(h[4*j+1], KC[j].y, hk1);                                \
        hk2 = fmaf(h[4*j+2], KC[j].z, hk2);                                \
        hk3 = fmaf(h[4*j+3], KC[j].w, hk3);                                \
        hq0 = fmaf(h[4*j+0], qb[j].x, hq0);                                \
        hq1 = fmaf(h[4*j+1], qb[j].y, hq1);                                \
        hq2 = fmaf(h[4*j+2], qb[j].z, hq2);                                \
        hq3 = fmaf(h[4*j+3], qb[j].w, hq3);                                \
    }                                                                      \
    float hk = (hk0+hk1)+(hk2+hk3);                                        \
    float hq = (hq0+hq1)+(hq2+hq3);                                        \
    /* 3. qb consumed -> prefetch q(t+1) into it (WAR, scoreboarded) */    \
    _Pragma("unroll")                                                      \
    for (int j = 0; j < 8; j++) qb[j] = qp[j];                             \
    /* 4. reduce over the 4 K-quarters (lanes l^1, l^2 share this v) */    \
    hk += __shfl_xor_sync(0xffffffffu, hk, 1);                             \
    hq += __shfl_xor_sync(0xffffffffu, hq, 1);                             \
    hk += __shfl_xor_sync(0xffffffffu, hk, 2);                             \
    hq += __shfl_xor_sync(0xffffffffu, hq, 2);                             \
    float eg = gb_c.x, beta = gb_c.y;                                      \
    float u  = fmaf(-eg, hk, vt_c) * beta;   /* (v - eg*(h.k)) * beta */   \
    float o  = fmaf(eg, hq, u * kq_c);       /* eg*(h.q) + u*(k.q)   */    \
    if (kh == 0) *op = o;                                                  \
    /* 5. pass2: h = eg*h + u*k (32 independent 2-op chains) */            \
    _Pragma("unroll")                                                      \
    for (int j = 0; j < 8; j++) {                                          \
        h[4*j+0] = fmaf(u, KC[j].x, eg*h[4*j+0]);                          \
        h[4*j+1] = fmaf(u, KC[j].y, eg*h[4*j+1]);                          \
        h[4*j+2] = fmaf(u, KC[j].z, eg*h[4*j+2]);                          \
        h[4*j+3] = fmaf(u, KC[j].w, eg*h[4*j+3]);                          \
    }                                                                      \
    /* 6. rotate carried scalars, advance pointers */                      \
    vt_c = vt_n; kq_c = kq_n; gb_c = gb_n;                                 \
    kp += KSTR; qp += KSTR; vp += HV_*V_; kqp += H_; gbp += HV_;           \
    op += HV_*V_;                                                          \
}

__global__ void __launch_bounds__(256, 1) gdn_recurrent(
    const float* __restrict__ vin,
    const float* __restrict__ h0src,
    const int*   __restrict__ h0idx,
    float* __restrict__ out)
{
    int blk   = blockIdx.x;
    int vhalf = blk & 1;
    int hv    = (blk >> 1) & (HV_ - 1);
    int b     = blk >> 4;
    int tid   = threadIdx.x;
    int kh    = tid & 3;
    int col   = tid >> 2;
    int v     = vhalf * 64 + col;
    int hh    = hv / REP_;

    // State: k indices [kh*32, kh*32+32)
    float h[32];
    int idx = h0idx[b];
    if (idx >= 0) {
        const float* src = h0src + (((size_t)idx * HV_ + hv) * K_ + (size_t)kh * 32) * V_ + v;
        #pragma unroll
        for (int i = 0; i < 32; i++) h[i] = src[(size_t)i * V_];
    } else {
        #pragma unroll
        for (int i = 0; i < 32; i++) h[i] = 0.0f;
    }

    const int KSTR = H_ * K_ / 4;   // float4 stride per t-step

    const float4* kp  = reinterpret_cast<const float4*>(g_kn + ((size_t)b*T_*H_ + hh)*K_) + kh*8;
    const float4* qp  = reinterpret_cast<const float4*>(g_qn + ((size_t)b*T_*H_ + hh)*K_) + kh*8;
    const float*  kqp = g_kq + (size_t)b*T_*H_ + hh;
    const float2* gbp = g_gb + (size_t)b*T_*HV_ + hv;
    const float*  vp  = vin  + ((size_t)b*T_*HV_ + hv)*V_ + v;
    float*        op  = out  + ((size_t)b*T_*HV_ + hv)*V_ + v;

    // Preload step 0 into buffer 0 + carried scalars; advance streams to t=1.
    float4 kb0[8], kb1[8], qb[8];
    #pragma unroll
    for (int j = 0; j < 8; j++) { kb0[j] = kp[j]; qb[j] = qp[j]; }
    float  vt_c = vp[0];
    float  kq_c = kqp[0];
    float2 gb_c = gbp[0];
    kp += KSTR; qp += KSTR; vp += HV_*V_; kqp += H_; gbp += HV_;

    #pragma unroll 1
    for (int t = 0; t < T_; t += 2) {
        STEP(kb0, kb1, true);            // step t   (t+1 < T always: T even)
        STEP(kb1, kb0, (t + 2 < T_));    // step t+1 (guard v-prefetch of t+2)
    }
}

// ---------------------------------------------------------------------------
// Inputs (metadata order): A_log, a, dt_bias, q, k, v, b,
//                          initial_state_source, initial_state_indices
// Output: float32 [B,T,HV,V]
// ---------------------------------------------------------------------------
extern "C" void kernel_launch(void* const* d_in, const int* in_sizes, int n_in,
                              void* d_out, int out_size) {
    const float* A_log = (const float*)d_in[0];
    const float* a     = (const float*)d_in[1];
    const float* dtb   = (const float*)d_in[2];
    const float* q     = (const float*)d_in[3];
    const float* k     = (const float*)d_in[4];
    const float* v     = (const float*)d_in[5];
    const float* bb    = (const float*)d_in[6];
    const float* h0    = (const float*)d_in[7];
    const int*   h0i   = (const int*)d_in[8];
    float* out = (float*)d_out;

    prep_qk<<<(B_ * T_ * H_) / 4, 128>>>(q, k);
    prep_gate<<<((size_t)B_ * T_ * HV_ + 255) / 256, 256>>>(A_log, a, dtb, bb);
    gdn_recurrent<<<B_ * HV_ * 2, 256>>>(v, h0, h0i, out);
}

// round 7
// speedup vs baseline: 1.6384x; 1.0194x over previous
#include <cuda_runtime.h>
#include <math.h>

#define B_  8
#define T_  4096
#define H_  4
#define HV_ 8
#define K_  128
#define V_  128
#define REP_ (HV_/H_)   // 2

// Scratch (static __device__ arrays: allocation-free per harness rules)
__device__ float  g_qn[(size_t)B_*T_*H_*K_];   // l2-normalized q * K^-0.5
__device__ float  g_kn[(size_t)B_*T_*H_*K_];   // l2-normalized k
__device__ float  g_kq[(size_t)B_*T_*H_];      // (qn . kn) per row
__device__ float2 g_gb[(size_t)B_*T_*HV_];     // {exp(g), sigmoid(b)}

// ---------------------------------------------------------------------------
// Prepass 1: per (b,t,h) row — l2norm q and k over K=128, fold scale into q,
// precompute kq = qn . kn (output shortcut for the scan).
// ---------------------------------------------------------------------------
__global__ void __launch_bounds__(128) prep_qk(const float* __restrict__ q,
                                               const float* __restrict__ k) {
    int warp = threadIdx.x >> 5;
    int lane = threadIdx.x & 31;
    size_t row = (size_t)blockIdx.x * 4 + warp;
    const float4* q4 = reinterpret_cast<const float4*>(q + row * K_);
    const float4* k4 = reinterpret_cast<const float4*>(k + row * K_);
    float4 qa = q4[lane];
    float4 ka = k4[lane];
    float sq = qa.x*qa.x + qa.y*qa.y + qa.z*qa.z + qa.w*qa.w;
    float sk = ka.x*ka.x + ka.y*ka.y + ka.z*ka.z + ka.w*ka.w;
    float dp = qa.x*ka.x + qa.y*ka.y + qa.z*ka.z + qa.w*ka.w;
    #pragma unroll
    for (int o = 16; o > 0; o >>= 1) {
        sq += __shfl_xor_sync(0xffffffffu, sq, o);
        sk += __shfl_xor_sync(0xffffffffu, sk, o);
        dp += __shfl_xor_sync(0xffffffffu, dp, o);
    }
    const float scale = 0.088388347648318440550f;   // 128^-0.5
    float iq = rsqrtf(sq + 1e-6f) * scale;
    float ik = rsqrtf(sk + 1e-6f);
    reinterpret_cast<float4*>(g_qn + row * K_)[lane] =
        make_float4(qa.x*iq, qa.y*iq, qa.z*iq, qa.w*iq);
    reinterpret_cast<float4*>(g_kn + row * K_)[lane] =
        make_float4(ka.x*ik, ka.y*ik, ka.z*ik, ka.w*ik);
    if (lane == 0) g_kq[row] = dp * iq * ik;
}

// ---------------------------------------------------------------------------
// Prepass 2: per (b,t,hv) — eg = exp(-exp(A_log)*softplus(a+dt_bias)),
// beta = sigmoid(b). Packed float2 -> one LDG.64 in the scan.
// ---------------------------------------------------------------------------
__global__ void __launch_bounds__(256) prep_gate(const float* __restrict__ A_log,
                                                 const float* __restrict__ a,
                                                 const float* __restrict__ dt_bias,
                                                 const float* __restrict__ b) {
    size_t i = (size_t)blockIdx.x * blockDim.x + threadIdx.x;
    if (i >= (size_t)B_*T_*HV_) return;
    int hv = (int)(i % HV_);
    float x = a[i] + dt_bias[hv];
    float sp = (x <= 20.0f) ? log1pf(expf(x)) : x;   // softplus, beta=1, thr=20
    float g  = -expf(A_log[hv]) * sp;
    float bt = 1.0f / (1.0f + expf(-b[i]));
    g_gb[i] = make_float2(expf(g), bt);
}

// ---------------------------------------------------------------------------
// Main persistent recurrence. grid = B*HV*2 = 128 CTAs, 512 threads
// (16 warps/CTA -> 4 warps/SMSP: latency hidden by warp parallelism,
//  NOT by register double-buffering — pressure kept ~90 regs/thread).
//   blockIdx.x: bit0 = v-half, bits[1:3] = hv, bits[4:6] = b
//   thread: ko = tid&7 (K-octant, 16 floats), col = tid>>3 (local V column)
// Per step:
//   load k,q octants + scalars -> two parallel dots (h.k, h.q, 4 accum chains)
//   -> 3-round shfl_xor reduce over 8 octants -> u,o scalars -> store (ko==0)
//   -> h = eg*h + u*k (16 independent 2-op chains)
// No __syncthreads, no MUFU, no prefetch buffers.
// ---------------------------------------------------------------------------
__global__ void __launch_bounds__(512, 1) gdn_recurrent(
    const float* __restrict__ vin,
    const float* __restrict__ h0src,
    const int*   __restrict__ h0idx,
    float* __restrict__ out)
{
    int blk   = blockIdx.x;
    int vhalf = blk & 1;
    int hv    = (blk >> 1) & (HV_ - 1);
    int b     = blk >> 4;
    int tid   = threadIdx.x;
    int ko    = tid & 7;          // K-octant
    int col   = tid >> 3;         // 0..63 local V column
    int v     = vhalf * 64 + col;
    int hh    = hv / REP_;

    // State: k indices [ko*16, ko*16+16)
    float h[16];
    int idx = h0idx[b];
    if (idx >= 0) {
        const float* src = h0src + (((size_t)idx * HV_ + hv) * K_ + (size_t)ko * 16) * V_ + v;
        #pragma unroll
        for (int i = 0; i < 16; i++) h[i] = src[(size_t)i * V_];
    } else {
        #pragma unroll
        for (int i = 0; i < 16; i++) h[i] = 0.0f;
    }

    const float4* kp  = reinterpret_cast<const float4*>(g_kn + ((size_t)b*T_*H_ + hh)*K_) + ko*4;
    const float4* qp  = reinterpret_cast<const float4*>(g_qn + ((size_t)b*T_*H_ + hh)*K_) + ko*4;
    const float*  kqp = g_kq + (size_t)b*T_*H_ + hh;
    const float2* gbp = g_gb + (size_t)b*T_*HV_ + hv;
    const float*  vp  = vin  + ((size_t)b*T_*HV_ + hv)*V_ + v;
    float*        op  = out  + ((size_t)b*T_*HV_ + hv)*V_ + v;

    const int KSTR = H_ * K_ / 4;   // float4 stride per t-step

    #pragma unroll 1
    for (int t = 0; t < T_; t++) {
        // Issue all loads up front (MLP=8 vector loads + 3 scalar streams)
        float4 k0 = kp[0], k1 = kp[1], k2 = kp[2], k3 = kp[3];
        float4 q0 = qp[0], q1 = qp[1], q2 = qp[2], q3 = qp[3];
        float2 gb = gbp[0];
        float  kq = kqp[0];
        float  vt = vp[0];

        // Two parallel dots vs h_old: hk = h.k_oct, hq = h.q_oct
        float hk0, hk1, hk2, hk3, hq0, hq1, hq2, hq3;
        hk0 = h[ 0]*k0.x; hk1 = h[ 1]*k0.y; hk2 = h[ 2]*k0.z; hk3 = h[ 3]*k0.w;
        hq0 = h[ 0]*q0.x; hq1 = h[ 1]*q0.y; hq2 = h[ 2]*q0.z; hq3 = h[ 3]*q0.w;
        hk0 = fmaf(h[ 4], k1.x, hk0); hk1 = fmaf(h[ 5], k1.y, hk1);
        hk2 = fmaf(h[ 6], k1.z, hk2); hk3 = fmaf(h[ 7], k1.w, hk3);
        hq0 = fmaf(h[ 4], q1.x, hq0); hq1 = fmaf(h[ 5], q1.y, hq1);
        hq2 = fmaf(h[ 6], q1.z, hq2); hq3 = fmaf(h[ 7], q1.w, hq3);
        hk0 = fmaf(h[ 8], k2.x, hk0); hk1 = fmaf(h[ 9], k2.y, hk1);
        hk2 = fmaf(h[10], k2.z, hk2); hk3 = fmaf(h[11], k2.w, hk3);
        hq0 = fmaf(h[ 8], q2.x, hq0); hq1 = fmaf(h[ 9], q2.y, hq1);
        hq2 = fmaf(h[10], q2.z, hq2); hq3 = fmaf(h[11], q2.w, hq3);
        hk0 = fmaf(h[12], k3.x, hk0); hk1 = fmaf(h[13], k3.y, hk1);
        hk2 = fmaf(h[14], k3.z, hk2); hk3 = fmaf(h[15], k3.w, hk3);
        hq0 = fmaf(h[12], q3.x, hq0); hq1 = fmaf(h[13], q3.y, hq1);
        hq2 = fmaf(h[14], q3.z, hq2); hq3 = fmaf(h[15], q3.w, hq3);
        float hk = (hk0 + hk1) + (hk2 + hk3);
        float hq = (hq0 + hq1) + (hq2 + hq3);

        // Reduce over the 8 K-octants (lanes differing in bits 0..2 share v)
        hk += __shfl_xor_sync(0xffffffffu, hk, 1);
        hq += __shfl_xor_sync(0xffffffffu, hq, 1);
        hk += __shfl_xor_sync(0xffffffffu, hk, 2);
        hq += __shfl_xor_sync(0xffffffffu, hq, 2);
        hk += __shfl_xor_sync(0xffffffffu, hk, 4);
        hq += __shfl_xor_sync(0xffffffffu, hq, 4);

        float eg = gb.x, beta = gb.y;
        float u  = fmaf(-eg, hk, vt) * beta;     // (v - eg*(h.k)) * beta
        float o  = fmaf(eg, hq, u * kq);         // eg*(h.q) + u*(k.q)
        if (ko == 0) *op = o;

        // Update: h = eg*h + u*k (16 independent 2-op chains)
        h[ 0] = fmaf(u, k0.x, eg*h[ 0]); h[ 1] = fmaf(u, k0.y, eg*h[ 1]);
        h[ 2] = fmaf(u, k0.z, eg*h[ 2]); h[ 3] = fmaf(u, k0.w, eg*h[ 3]);
        h[ 4] = fmaf(u, k1.x, eg*h[ 4]); h[ 5] = fmaf(u, k1.y, eg*h[ 5]);
        h[ 6] = fmaf(u, k1.z, eg*h[ 6]); h[ 7] = fmaf(u, k1.w, eg*h[ 7]);
        h[ 8] = fmaf(u, k2.x, eg*h[ 8]); h[ 9] = fmaf(u, k2.y, eg*h[ 9]);
        h[10] = fmaf(u, k2.z, eg*h[10]); h[11] = fmaf(u, k2.w, eg*h[11]);
        h[12] = fmaf(u, k3.x, eg*h[12]); h[13] = fmaf(u, k3.y, eg*h[13]);
        h[14] = fmaf(u, k3.z, eg*h[14]); h[15] = fmaf(u, k3.w, eg*h[15]);

        kp  += KSTR;
        qp  += KSTR;
        kqp += H_;
        gbp += HV_;
        vp  += HV_ * V_;
        op  += HV_ * V_;
    }
}

// ---------------------------------------------------------------------------
// Inputs (metadata order): A_log, a, dt_bias, q, k, v, b,
//                          initial_state_source, initial_state_indices
// Output: float32 [B,T,HV,V]
// ---------------------------------------------------------------------------
extern "C" void kernel_launch(void* const* d_in, const int* in_sizes, int n_in,
                              void* d_out, int out_size) {
    const float* A_log = (const float*)d_in[0];
    const float* a     = (const float*)d_in[1];
    const float* dtb   = (const float*)d_in[2];
    const float* q     = (const float*)d_in[3];
    const float* k     = (const float*)d_in[4];
    const float* v     = (const float*)d_in[5];
    const float* bb    = (const float*)d_in[6];
    const float* h0    = (const float*)d_in[7];
    const int*   h0i   = (const int*)d_in[8];
    float* out = (float*)d_out;

    prep_qk<<<(B_ * T_ * H_) / 4, 128>>>(q, k);
    prep_gate<<<((size_t)B_ * T_ * HV_ + 255) / 256, 256>>>(A_log, a, dtb, bb);
    gdn_recurrent<<<B_ * HV_ * 2, 512>>>(v, h0, h0i, out);
}

// round 8
// speedup vs baseline: 2.1078x; 1.2865x over previous
#include <cuda_runtime.h>
#include <math.h>

#define B_  8
#define T_  4096
#define H_  4
#define HV_ 8
#define K_  128
#define V_  128
#define REP_ (HV_/H_)   // 2

// Scratch (static __device__ arrays: allocation-free per harness rules)
__device__ float  g_qn[(size_t)B_*T_*H_*K_];   // l2-normalized q * K^-0.5
__device__ float  g_kn[(size_t)B_*T_*H_*K_];   // l2-normalized k
__device__ float  g_kq[(size_t)B_*T_*H_];      // (qn . kn) per row
__device__ float2 g_gb[(size_t)B_*T_*HV_];     // {exp(g), sigmoid(b)}

// ---------------------------------------------------------------------------
// Prepass 1: per (b,t,h) row — l2norm q and k over K=128, fold scale into q,
// precompute kq = qn . kn (output shortcut for the scan).
// ---------------------------------------------------------------------------
__global__ void __launch_bounds__(128) prep_qk(const float* __restrict__ q,
                                               const float* __restrict__ k) {
    int warp = threadIdx.x >> 5;
    int lane = threadIdx.x & 31;
    size_t row = (size_t)blockIdx.x * 4 + warp;
    const float4* q4 = reinterpret_cast<const float4*>(q + row * K_);
    const float4* k4 = reinterpret_cast<const float4*>(k + row * K_);
    float4 qa = q4[lane];
    float4 ka = k4[lane];
    float sq = qa.x*qa.x + qa.y*qa.y + qa.z*qa.z + qa.w*qa.w;
    float sk = ka.x*ka.x + ka.y*ka.y + ka.z*ka.z + ka.w*ka.w;
    float dp = qa.x*ka.x + qa.y*ka.y + qa.z*ka.z + qa.w*ka.w;
    #pragma unroll
    for (int o = 16; o > 0; o >>= 1) {
        sq += __shfl_xor_sync(0xffffffffu, sq, o);
        sk += __shfl_xor_sync(0xffffffffu, sk, o);
        dp += __shfl_xor_sync(0xffffffffu, dp, o);
    }
    const float scale = 0.088388347648318440550f;   // 128^-0.5
    float iq = rsqrtf(sq + 1e-6f) * scale;
    float ik = rsqrtf(sk + 1e-6f);
    reinterpret_cast<float4*>(g_qn + row * K_)[lane] =
        make_float4(qa.x*iq, qa.y*iq, qa.z*iq, qa.w*iq);
    reinterpret_cast<float4*>(g_kn + row * K_)[lane] =
        make_float4(ka.x*ik, ka.y*ik, ka.z*ik, ka.w*ik);
    if (lane == 0) g_kq[row] = dp * iq * ik;
}

// ---------------------------------------------------------------------------
// Prepass 2: per (b,t,hv) — eg = exp(-exp(A_log)*softplus(a+dt_bias)),
// beta = sigmoid(b). Packed float2 -> one LDG.64 in the scan.
// ---------------------------------------------------------------------------
__global__ void __launch_bounds__(256) prep_gate(const float* __restrict__ A_log,
                                                 const float* __restrict__ a,
                                                 const float* __restrict__ dt_bias,
                                                 const float* __restrict__ b) {
    size_t i = (size_t)blockIdx.x * blockDim.x + threadIdx.x;
    if (i >= (size_t)B_*T_*HV_) return;
    int hv = (int)(i % HV_);
    float x = a[i] + dt_bias[hv];
    float sp = (x <= 20.0f) ? log1pf(expf(x)) : x;   // softplus, beta=1, thr=20
    float g  = -expf(A_log[hv]) * sp;
    float bt = 1.0f / (1.0f + expf(-b[i]));
    g_gb[i] = make_float2(expf(g), bt);
}

// ---------------------------------------------------------------------------
// Main persistent recurrence. grid = B*HV*2 = 128 CTAs, 256 threads
// (8 warps/CTA -> 2 warps/SMSP).
//   blockIdx.x: bit0 = v-half, bits[1:3] = hv, bits[4:6] = b
//   thread: ko = tid&7 (K-octant, 16 k-rows), vg = tid>>3 (2 adjacent V cols)
// 2-D state tile per thread: h[16][2] = 32 regs. This halves redundant k/q
// load traffic per FMA vs a 1-D column split (L1tex wavefronts ~270/step/SM
// vs the 512-cyc FMA issue floor -> FMA-bound, not L1-bound).
// Per step:
//   load k,q octants (4+4 LDG.128) + v (LDG.64) + scalars
//   -> dots h.k, h.q for both v-cols (64 FMA, 8 indep chains)
//   -> 3-round shfl_xor reduce over the 8 K-octants
//   -> u,o per col -> STG.64 (ko==0) -> h = eg*h + u*k (64 FMA)
// No __syncthreads, no MUFU.
// ---------------------------------------------------------------------------
__global__ void __launch_bounds__(256, 1) gdn_recurrent(
    const float* __restrict__ vin,
    const float* __restrict__ h0src,
    const int*   __restrict__ h0idx,
    float* __restrict__ out)
{
    int blk   = blockIdx.x;
    int vhalf = blk & 1;
    int hv    = (blk >> 1) & (HV_ - 1);
    int b     = blk >> 4;
    int tid   = threadIdx.x;
    int ko    = tid & 7;          // K-octant: rows [ko*16, ko*16+16)
    int vg    = tid >> 3;         // 0..31 -> V columns vg*2, vg*2+1
    int v0    = vhalf * 64 + vg * 2;
    int hh    = hv / REP_;

    // State tile: h[i] holds k-row (ko*16+i), columns (v0, v0+1)
    float2 h[16];
    int idx = h0idx[b];
    if (idx >= 0) {
        const float* src = h0src + (((size_t)idx * HV_ + hv) * K_ + (size_t)ko * 16) * V_ + v0;
        #pragma unroll
        for (int i = 0; i < 16; i++)
            h[i] = *reinterpret_cast<const float2*>(src + (size_t)i * V_);
    } else {
        #pragma unroll
        for (int i = 0; i < 16; i++) h[i] = make_float2(0.f, 0.f);
    }

    const float4* kp  = reinterpret_cast<const float4*>(g_kn + ((size_t)b*T_*H_ + hh)*K_) + ko*4;
    const float4* qp  = reinterpret_cast<const float4*>(g_qn + ((size_t)b*T_*H_ + hh)*K_) + ko*4;
    const float*  kqp = g_kq + (size_t)b*T_*H_ + hh;
    const float2* gbp = g_gb + (size_t)b*T_*HV_ + hv;
    const float2* vp  = reinterpret_cast<const float2*>(vin + ((size_t)b*T_*HV_ + hv)*V_ + v0);
    float2*       op  = reinterpret_cast<float2*>(out + ((size_t)b*T_*HV_ + hv)*V_ + v0);

    const int KSTR = H_ * K_ / 4;       // float4 stride per t-step
    const int VSTR = HV_ * V_ / 2;      // float2 stride per t-step

    #pragma unroll 1
    for (int t = 0; t < T_; t++) {
        // Issue all loads up front (MLP: 8 LDG.128 + 4 scalar-ish streams)
        float4 kk[4], qq[4];
        #pragma unroll
        for (int j = 0; j < 4; j++) { kk[j] = kp[j]; qq[j] = qp[j]; }
        float2 gb = gbp[0];
        float  kq = kqp[0];
        float2 vt = vp[0];

        // Dots vs h_old for both columns: hk[c] = h[:,c].k_oct, hq[c] = h[:,c].q_oct
        // 8 independent accumulator chains (2 per dot per column).
        float hk0a=0.f, hk0b=0.f, hk1a=0.f, hk1b=0.f;
        float hq0a=0.f, hq0b=0.f, hq1a=0.f, hq1b=0.f;
        #pragma unroll
        for (int j = 0; j < 4; j++) {
            float4 kv = kk[j], qv = qq[j];
            float2 ha = h[4*j+0], hb = h[4*j+1], hc = h[4*j+2], hd = h[4*j+3];
            hk0a = fmaf(ha.x, kv.x, hk0a); hk1a = fmaf(ha.y, kv.x, hk1a);
            hq0a = fmaf(ha.x, qv.x, hq0a); hq1a = fmaf(ha.y, qv.x, hq1a);
            hk0b = fmaf(hb.x, kv.y, hk0b); hk1b = fmaf(hb.y, kv.y, hk1b);
            hq0b = fmaf(hb.x, qv.y, hq0b); hq1b = fmaf(hb.y, qv.y, hq1b);
            hk0a = fmaf(hc.x, kv.z, hk0a); hk1a = fmaf(hc.y, kv.z, hk1a);
            hq0a = fmaf(hc.x, qv.z, hq0a); hq1a = fmaf(hc.y, qv.z, hq1a);
            hk0b = fmaf(hd.x, kv.w, hk0b); hk1b = fmaf(hd.y, kv.w, hk1b);
            hq0b = fmaf(hd.x, qv.w, hq0b); hq1b = fmaf(hd.y, qv.w, hq1b);
        }
        float hk0 = hk0a + hk0b, hk1 = hk1a + hk1b;
        float hq0 = hq0a + hq0b, hq1 = hq1a + hq1b;

        // Reduce over the 8 K-octants (xor lanes bits 0..2; vg untouched)
        #pragma unroll
        for (int m = 1; m <= 4; m <<= 1) {
            hk0 += __shfl_xor_sync(0xffffffffu, hk0, m);
            hk1 += __shfl_xor_sync(0xffffffffu, hk1, m);
            hq0 += __shfl_xor_sync(0xffffffffu, hq0, m);
            hq1 += __shfl_xor_sync(0xffffffffu, hq1, m);
        }

        float eg = gb.x, beta = gb.y;
        float u0 = fmaf(-eg, hk0, vt.x) * beta;   // (v - eg*(h.k)) * beta
        float u1 = fmaf(-eg, hk1, vt.y) * beta;
        if (ko == 0) {
            float2 o;
            o.x = fmaf(eg, hq0, u0 * kq);         // eg*(h.q) + u*(k.q)
            o.y = fmaf(eg, hq1, u1 * kq);
            *op = o;
        }

        // Update: h = eg*h + u*k (32 independent 2-op chains)
        #pragma unroll
        for (int j = 0; j < 4; j++) {
            float4 kv = kk[j];
            h[4*j+0].x = fmaf(u0, kv.x, eg*h[4*j+0].x);
            h[4*j+0].y = fmaf(u1, kv.x, eg*h[4*j+0].y);
            h[4*j+1].x = fmaf(u0, kv.y, eg*h[4*j+1].x);
            h[4*j+1].y = fmaf(u1, kv.y, eg*h[4*j+1].y);
            h[4*j+2].x = fmaf(u0, kv.z, eg*h[4*j+2].x);
            h[4*j+2].y = fmaf(u1, kv.z, eg*h[4*j+2].y);
            h[4*j+3].x = fmaf(u0, kv.w, eg*h[4*j+3].x);
            h[4*j+3].y = fmaf(u1, kv.w, eg*h[4*j+3].y);
        }

        kp  += KSTR;
        qp  += KSTR;
        kqp += H_;
        gbp += HV_;
        vp  += VSTR;
        op  += VSTR;
    }
}

// ---------------------------------------------------------------------------
// Inputs (metadata order): A_log, a, dt_bias, q, k, v, b,
//                          initial_state_source, initial_state_indices
// Output: float32 [B,T,HV,V]
// ---------------------------------------------------------------------------
extern "C" void kernel_launch(void* const* d_in, const int* in_sizes, int n_in,
                              void* d_out, int out_size) {
    const float* A_log = (const float*)d_in[0];
    const float* a     = (const float*)d_in[1];
    const float* dtb   = (const float*)d_in[2];
    const float* q     = (const float*)d_in[3];
    const float* k     = (const float*)d_in[4];
    const float* v     = (const float*)d_in[5];
    const float* bb    = (const float*)d_in[6];
    const float* h0    = (const float*)d_in[7];
    const int*   h0i   = (const int*)d_in[8];
    float* out = (float*)d_out;

    prep_qk<<<(B_ * T_ * H_) / 4, 128>>>(q, k);
    prep_gate<<<((size_t)B_ * T_ * HV_ + 255) / 256, 256>>>(A_log, a, dtb, bb);
    gdn_recurrent<<<B_ * HV_ * 2, 256>>>(v, h0, h0i, out);
}

// round 10
// speedup vs baseline: 2.6688x; 1.2661x over previous
#include <cuda_runtime.h>
#include <math.h>

#define B_  8
#define T_  4096
#define H_  4
#define HV_ 8
#define K_  128
#define V_  128
#define REP_ (HV_/H_)   // 2
#define S_  (T_/2)      // fused 2-step groups
#define PFG 4           // prefetch distance in groups (8 t-steps)

// Scratch (static __device__ arrays: allocation-free per harness rules).
// k/q streams padded 8 t-rows so the L2 prefetch never leaves the allocation.
__device__ float  g_qn[(size_t)B_*T_*H_*K_ + 8*H_*K_];  // l2norm q * K^-0.5
__device__ float  g_kn[(size_t)B_*T_*H_*K_ + 8*H_*K_];  // l2norm k
__device__ float4 g_d  [(size_t)B_*S_*H_];    // {k1.q1, k1.k2, k1.q2, k2.q2}
__device__ float4 g_gb4[(size_t)B_*S_*HV_];   // {eg1, beta1, eg2, beta2}

// ---------------------------------------------------------------------------
// Prepass 1: per (b,t,h) row — l2norm q and k over K=128, fold scale into q.
// ---------------------------------------------------------------------------
__global__ void __launch_bounds__(128) prep_qk(const float* __restrict__ q,
                                               const float* __restrict__ k) {
    int warp = threadIdx.x >> 5;
    int lane = threadIdx.x & 31;
    size_t row = (size_t)blockIdx.x * 4 + warp;
    const float4* q4 = reinterpret_cast<const float4*>(q + row * K_);
    const float4* k4 = reinterpret_cast<const float4*>(k + row * K_);
    float4 qa = q4[lane];
    float4 ka = k4[lane];
    float sq = qa.x*qa.x + qa.y*qa.y + qa.z*qa.z + qa.w*qa.w;
    float sk = ka.x*ka.x + ka.y*ka.y + ka.z*ka.z + ka.w*ka.w;
    #pragma unroll
    for (int o = 16; o > 0; o >>= 1) {
        sq += __shfl_xor_sync(0xffffffffu, sq, o);
        sk += __shfl_xor_sync(0xffffffffu, sk, o);
    }
    const float scale = 0.088388347648318440550f;   // 128^-0.5
    float iq = rsqrtf(sq + 1e-6f) * scale;
    float ik = rsqrtf(sk + 1e-6f);
    reinterpret_cast<float4*>(g_qn + row * K_)[lane] =
        make_float4(qa.x*iq, qa.y*iq, qa.z*iq, qa.w*iq);
    reinterpret_cast<float4*>(g_kn + row * K_)[lane] =
        make_float4(ka.x*ik, ka.y*ik, ka.z*ik, ka.w*ik);
}

// ---------------------------------------------------------------------------
// Prepass 1b: per group (b,s,h) — the 4 cross dots among the normalized rows
// of t1=2s and t2=2s+1: {k1.q1, k1.k2, k1.q2, k2.q2}. One warp per group.
// ---------------------------------------------------------------------------
__global__ void __launch_bounds__(128) prep_dots() {
    int warp = threadIdx.x >> 5;
    int lane = threadIdx.x & 31;
    size_t gid = (size_t)blockIdx.x * 4 + warp;      // (b*S + s)*H + hh
    size_t hh   = gid % H_;
    size_t row1 = (gid / H_) * 2 * H_ + hh;          // (b*T + 2s)*H + hh
    const float4* k1p = reinterpret_cast<const float4*>(g_kn + row1 * K_);
    const float4* q1p = reinterpret_cast<const float4*>(g_qn + row1 * K_);
    const float4* k2p = reinterpret_cast<const float4*>(g_kn + (row1 + H_) * K_);
    const float4* q2p = reinterpret_cast<const float4*>(g_qn + (row1 + H_) * K_);
    float4 k1 = k1p[lane], q1 = q1p[lane], k2 = k2p[lane], q2 = q2p[lane];
    float d0 = k1.x*q1.x + k1.y*q1.y + k1.z*q1.z + k1.w*q1.w;
    float d1 = k1.x*k2.x + k1.y*k2.y + k1.z*k2.z + k1.w*k2.w;
    float d2 = k1.x*q2.x + k1.y*q2.y + k1.z*q2.z + k1.w*q2.w;
    float d3 = k2.x*q2.x + k2.y*q2.y + k2.z*q2.z + k2.w*q2.w;
    #pragma unroll
    for (int o = 16; o > 0; o >>= 1) {
        d0 += __shfl_xor_sync(0xffffffffu, d0, o);
        d1 += __shfl_xor_sync(0xffffffffu, d1, o);
        d2 += __shfl_xor_sync(0xffffffffu, d2, o);
        d3 += __shfl_xor_sync(0xffffffffu, d3, o);
    }
    if (lane == 0) g_d[gid] = make_float4(d0, d1, d2, d3);
}

// ---------------------------------------------------------------------------
// Prepass 2: per group (b,s,hv) — gates for both steps packed as one float4.
// ---------------------------------------------------------------------------
__global__ void __launch_bounds__(256) prep_gate4(const float* __restrict__ A_log,
                                                  const float* __restrict__ a,
                                                  const float* __restrict__ dt_bias,
                                                  const float* __restrict__ b) {
    size_t i = (size_t)blockIdx.x * blockDim.x + threadIdx.x;   // (b*S+s)*HV+hv
    if (i >= (size_t)B_*S_*HV_) return;
    int    hv = (int)(i % HV_);
    size_t bs = i / HV_;
    float  Ae = expf(A_log[hv]);
    float4 r;
    #pragma unroll
    for (int u = 0; u < 2; u++) {
        size_t idx = (2*bs + u) * HV_ + hv;          // (b*T + 2s+u)*HV + hv
        float x  = a[idx] + dt_bias[hv];
        float sp = (x <= 20.0f) ? log1pf(expf(x)) : x;   // softplus
        float eg = expf(-Ae * sp);
        float bt = 1.0f / (1.0f + expf(-b[idx]));
        if (u == 0) { r.x = eg; r.y = bt; } else { r.z = eg; r.w = bt; }
    }
    g_gb4[i] = r;
}

// ---------------------------------------------------------------------------
// Main persistent recurrence, 2-step fused. grid = 128 CTAs, 256 threads.
//   blockIdx.x: bit0 = v-half, bits[1:3] = hv, bits[4:6] = b
//   thread: ko = tid&7 (16 k-rows), vg = tid>>3 (2 adjacent V cols)
// Per group (2 steps): load k1,k2,q1,q2 octants + v pair + d + gates;
//   4 dots vs old h (both cols) -> ONE batched 3-round shfl reduce (8 vals)
//   -> scalar cascade u1,o1,u2,o2 (cross terms from precomputed d)
//   -> h = (eg1*eg2)h + (eg2*u1)k1 + u2*k2  (3 FMA/elem per 2 steps)
//   + L2 prefetch of k/q 4 groups ahead (stream is DRAM-resident; CTAs drift).
// ---------------------------------------------------------------------------
__global__ void __launch_bounds__(256, 1) gdn_recurrent(
    const float* __restrict__ vin,
    const float* __restrict__ h0src,
    const int*   __restrict__ h0idx,
    float* __restrict__ out)
{
    int blk   = blockIdx.x;
    int vhalf = blk & 1;
    int hv    = (blk >> 1) & (HV_ - 1);
    int b     = blk >> 4;
    int tid   = threadIdx.x;
    int ko    = tid & 7;          // K-octant: rows [ko*16, ko*16+16)
    int vg    = tid >> 3;         // 0..31 -> V columns vg*2, vg*2+1
    int v0    = vhalf * 64 + vg * 2;
    int hh    = hv / REP_;

    // State tile: h[i] = k-row (ko*16+i), columns (v0, v0+1)
    float2 h[16];
    int idx = h0idx[b];
    if (idx >= 0) {
        const float* src = h0src + (((size_t)idx * HV_ + hv) * K_ + (size_t)ko * 16) * V_ + v0;
        #pragma unroll
        for (int i = 0; i < 16; i++)
            h[i] = *reinterpret_cast<const float2*>(src + (size_t)i * V_);
    } else {
        #pragma unroll
        for (int i = 0; i < 16; i++) h[i] = make_float2(0.f, 0.f);
    }

    const int KSTR = H_ * K_ / 4;       // float4 stride per t-step
    const int VSTR = HV_ * V_ / 2;      // float2 stride per t-step

    const float4* kp  = reinterpret_cast<const float4*>(g_kn + ((size_t)b*T_*H_ + hh)*K_) + ko*4;
    const float4* qp  = reinterpret_cast<const float4*>(g_qn + ((size_t)b*T_*H_ + hh)*K_) + ko*4;
    const float4* ddp = g_d   + (size_t)b*S_*H_  + hh;
    const float4* gbp = g_gb4 + (size_t)b*S_*HV_ + hv;
    const float2* vp  = reinterpret_cast<const float2*>(vin + ((size_t)b*T_*HV_ + hv)*V_ + v0);
    float2*       op  = reinterpret_cast<float2*>(out + ((size_t)b*T_*HV_ + hv)*V_ + v0);

    #pragma unroll 1
    for (int s = 0; s < S_; s++) {
        // L2 prefetch of this thread's k/q addresses 4 groups (8 steps) ahead.
        asm volatile("prefetch.global.L2 [%0];" :: "l"((const void*)(kp + 2*PFG*KSTR)));
        asm volatile("prefetch.global.L2 [%0];" :: "l"((const void*)(qp + 2*PFG*KSTR)));

        // Batched loads for both steps (MLP = 16 LDG.128 + small streams)
        float4 k1[4], k2[4], q1[4], q2[4];
        #pragma unroll
        for (int j = 0; j < 4; j++) {
            k1[j] = kp[j];        q1[j] = qp[j];
            k2[j] = kp[KSTR + j]; q2[j] = qp[KSTR + j];
        }
        float4 dd = ddp[0];       // {k1.q1, k1.k2, k1.q2, k2.q2}
        float4 gg = gbp[0];       // {eg1, beta1, eg2, beta2}
        float2 v1 = vp[0];
        float2 v2 = vp[VSTR];

        // 4 dots vs OLD h, both columns: 8 accumulators, 16-deep chains each
        float k1x=0.f,k1y=0.f,k2x=0.f,k2y=0.f,q1x=0.f,q1y=0.f,q2x=0.f,q2y=0.f;
        #pragma unroll
        for (int j = 0; j < 4; j++) {
            #pragma unroll
            for (int r = 0; r < 4; r++) {
                float2 hr = h[4*j + r];
                float kc1 = (r==0)?k1[j].x:(r==1)?k1[j].y:(r==2)?k1[j].z:k1[j].w;
                float kc2 = (r==0)?k2[j].x:(r==1)?k2[j].y:(r==2)?k2[j].z:k2[j].w;
                float qc1 = (r==0)?q1[j].x:(r==1)?q1[j].y:(r==2)?q1[j].z:q1[j].w;
                float qc2 = (r==0)?q2[j].x:(r==1)?q2[j].y:(r==2)?q2[j].z:q2[j].w;
                k1x = fmaf(hr.x, kc1, k1x);  k1y = fmaf(hr.y, kc1, k1y);
                k2x = fmaf(hr.x, kc2, k2x);  k2y = fmaf(hr.y, kc2, k2y);
                q1x = fmaf(hr.x, qc1, q1x);  q1y = fmaf(hr.y, qc1, q1y);
                q2x = fmaf(hr.x, qc2, q2x);  q2y = fmaf(hr.y, qc2, q2y);
            }
        }

        // One batched reduce over the 8 K-octants (lane bits 0..2)
        #pragma unroll
        for (int m = 1; m <= 4; m <<= 1) {
            k1x += __shfl_xor_sync(0xffffffffu, k1x, m);
            k1y += __shfl_xor_sync(0xffffffffu, k1y, m);
            k2x += __shfl_xor_sync(0xffffffffu, k2x, m);
            k2y += __shfl_xor_sync(0xffffffffu, k2y, m);
            q1x += __shfl_xor_sync(0xffffffffu, q1x, m);
            q1y += __shfl_xor_sync(0xffffffffu, q1y, m);
            q2x += __shfl_xor_sync(0xffffffffu, q2x, m);
            q2y += __shfl_xor_sync(0xffffffffu, q2y, m);
        }

        float eg1 = gg.x, b1 = gg.y, eg2 = gg.z, b2 = gg.w;
        // Step 1 scalars
        float u1x = fmaf(-eg1, k1x, v1.x) * b1;
        float u1y = fmaf(-eg1, k1y, v1.y) * b1;
        // Bridge: h1.k2 = eg1*(h.k2) + u1*(k1.k2); h1.q2 analog
        float hk2x = fmaf(u1x, dd.y, eg1 * k2x);
        float hk2y = fmaf(u1y, dd.y, eg1 * k2y);
        // Step 2 scalars
        float u2x = fmaf(-eg2, hk2x, v2.x) * b2;
        float u2y = fmaf(-eg2, hk2y, v2.y) * b2;

        if (ko == 0) {
            float2 o1, o2;
            o1.x = fmaf(eg1, q1x, u1x * dd.x);                    // eg1*h.q1 + u1*k1q1
            o1.y = fmaf(eg1, q1y, u1y * dd.x);
            float hq2x = fmaf(u1x, dd.z, eg1 * q2x);              // h1.q2
            float hq2y = fmaf(u1y, dd.z, eg1 * q2y);
            o2.x = fmaf(eg2, hq2x, u2x * dd.w);                   // eg2*h1.q2 + u2*k2q2
            o2.y = fmaf(eg2, hq2y, u2y * dd.w);
            op[0]    = o1;
            op[VSTR] = o2;
        }

        // Fused update: h = (eg1*eg2)h + (eg2*u1)k1 + u2*k2
        float e12 = eg1 * eg2;
        float c1x = eg2 * u1x, c1y = eg2 * u1y;
        #pragma unroll
        for (int j = 0; j < 4; j++) {
            #pragma unroll
            for (int r = 0; r < 4; r++) {
                float kc1 = (r==0)?k1[j].x:(r==1)?k1[j].y:(r==2)?k1[j].z:k1[j].w;
                float kc2 = (r==0)?k2[j].x:(r==1)?k2[j].y:(r==2)?k2[j].z:k2[j].w;
                float2 hr = h[4*j + r];
                hr.x = fmaf(kc2, u2x, fmaf(kc1, c1x, e12 * hr.x));
                hr.y = fmaf(kc2, u2y, fmaf(kc1, c1y, e12 * hr.y));
                h[4*j + r] = hr;
            }
        }

        kp  += 2 * KSTR;
        qp  += 2 * KSTR;
        ddp += H_;
        gbp += HV_;
        vp  += 2 * VSTR;
        op  += 2 * VSTR;
    }
}

// ---------------------------------------------------------------------------
// Inputs (metadata order): A_log, a, dt_bias, q, k, v, b,
//                          initial_state_source, initial_state_indices
// Output: float32 [B,T,HV,V]
// ---------------------------------------------------------------------------
extern "C" void kernel_launch(void* const* d_in, const int* in_sizes, int n_in,
                              void* d_out, int out_size) {
    const float* A_log = (const float*)d_in[0];
    const float* a     = (const float*)d_in[1];
    const float* dtb   = (const float*)d_in[2];
    const float* q     = (const float*)d_in[3];
    const float* k     = (const float*)d_in[4];
    const float* v     = (const float*)d_in[5];
    const float* bb    = (const float*)d_in[6];
    const float* h0    = (const float*)d_in[7];
    const int*   h0i   = (const int*)d_in[8];
    float* out = (float*)d_out;

    prep_qk<<<(B_ * T_ * H_) / 4, 128>>>(q, k);
    prep_dots<<<(B_ * S_ * H_) / 4, 128>>>();
    prep_gate4<<<((size_t)B_ * S_ * HV_ + 255) / 256, 256>>>(A_log, a, dtb, bb);
    gdn_recurrent<<<B_ * HV_ * 2, 256>>>(v, h0, h0i, out);
}

// round 11
// speedup vs baseline: 4.7894x; 1.7946x over previous
#include <cuda_runtime.h>
#include <math.h>

#define B_  8
#define T_  4096
#define H_  4
#define HV_ 8
#define K_  128
#define V_  128
#define REP_ (HV_/H_)   // 2
#define S_  (T_/2)      // fused 2-step groups
#define CHS 16          // steps per smem chunk
#define CHG (CHS/2)     // groups per chunk = 8
#define NCH (T_/CHS)    // 256 chunks

// smem swizzle: stream row = 8 octants * 80B (pad 16B) = 640B; step = 1280B.
#define ROWB  640
#define STEPB 1280
#define BUFB  (CHS*STEPB)   // 20480B per buffer, x2 double-buffered

// Scratch (static __device__ arrays: allocation-free per harness rules)
__device__ float  g_qn[(size_t)B_*T_*H_*K_];  // l2norm q * K^-0.5
__device__ float  g_kn[(size_t)B_*T_*H_*K_];  // l2norm k
__device__ float4 g_d  [(size_t)B_*S_*H_];    // {k1.q1, k1.k2, k1.q2, k2.q2}
__device__ float4 g_gb4[(size_t)B_*S_*HV_];   // {eg1, beta1, eg2, beta2}

// ---------------------------------------------------------------------------
// Prepass 1: per (b,t,h) row — l2norm q and k over K=128, fold scale into q.
// ---------------------------------------------------------------------------
__global__ void __launch_bounds__(128) prep_qk(const float* __restrict__ q,
                                               const float* __restrict__ k) {
    int warp = threadIdx.x >> 5;
    int lane = threadIdx.x & 31;
    size_t row = (size_t)blockIdx.x * 4 + warp;
    const float4* q4 = reinterpret_cast<const float4*>(q + row * K_);
    const float4* k4 = reinterpret_cast<const float4*>(k + row * K_);
    float4 qa = q4[lane];
    float4 ka = k4[lane];
    float sq = qa.x*qa.x + qa.y*qa.y + qa.z*qa.z + qa.w*qa.w;
    float sk = ka.x*ka.x + ka.y*ka.y + ka.z*ka.z + ka.w*ka.w;
    #pragma unroll
    for (int o = 16; o > 0; o >>= 1) {
        sq += __shfl_xor_sync(0xffffffffu, sq, o);
        sk += __shfl_xor_sync(0xffffffffu, sk, o);
    }
    const float scale = 0.088388347648318440550f;   // 128^-0.5
    float iq = rsqrtf(sq + 1e-6f) * scale;
    float ik = rsqrtf(sk + 1e-6f);
    reinterpret_cast<float4*>(g_qn + row * K_)[lane] =
        make_float4(qa.x*iq, qa.y*iq, qa.z*iq, qa.w*iq);
    reinterpret_cast<float4*>(g_kn + row * K_)[lane] =
        make_float4(ka.x*ik, ka.y*ik, ka.z*ik, ka.w*ik);
}

// ---------------------------------------------------------------------------
// Prepass 1b: per group (b,s,h) — cross dots {k1.q1, k1.k2, k1.q2, k2.q2}.
// ---------------------------------------------------------------------------
__global__ void __launch_bounds__(128) prep_dots() {
    int warp = threadIdx.x >> 5;
    int lane = threadIdx.x & 31;
    size_t gid = (size_t)blockIdx.x * 4 + warp;      // (b*S + s)*H + hh
    size_t hh   = gid % H_;
    size_t row1 = (gid / H_) * 2 * H_ + hh;          // (b*T + 2s)*H + hh
    const float4* k1p = reinterpret_cast<const float4*>(g_kn + row1 * K_);
    const float4* q1p = reinterpret_cast<const float4*>(g_qn + row1 * K_);
    const float4* k2p = reinterpret_cast<const float4*>(g_kn + (row1 + H_) * K_);
    const float4* q2p = reinterpret_cast<const float4*>(g_qn + (row1 + H_) * K_);
    float4 k1 = k1p[lane], q1 = q1p[lane], k2 = k2p[lane], q2 = q2p[lane];
    float d0 = k1.x*q1.x + k1.y*q1.y + k1.z*q1.z + k1.w*q1.w;
    float d1 = k1.x*k2.x + k1.y*k2.y + k1.z*k2.z + k1.w*k2.w;
    float d2 = k1.x*q2.x + k1.y*q2.y + k1.z*q2.z + k1.w*q2.w;
    float d3 = k2.x*q2.x + k2.y*q2.y + k2.z*q2.z + k2.w*q2.w;
    #pragma unroll
    for (int o = 16; o > 0; o >>= 1) {
        d0 += __shfl_xor_sync(0xffffffffu, d0, o);
        d1 += __shfl_xor_sync(0xffffffffu, d1, o);
        d2 += __shfl_xor_sync(0xffffffffu, d2, o);
        d3 += __shfl_xor_sync(0xffffffffu, d3, o);
    }
    if (lane == 0) g_d[gid] = make_float4(d0, d1, d2, d3);
}

// ---------------------------------------------------------------------------
// Prepass 2: per group (b,s,hv) — gates for both steps packed as one float4.
// ---------------------------------------------------------------------------
__global__ void __launch_bounds__(256) prep_gate4(const float* __restrict__ A_log,
                                                  const float* __restrict__ a,
                                                  const float* __restrict__ dt_bias,
                                                  const float* __restrict__ b) {
    size_t i = (size_t)blockIdx.x * blockDim.x + threadIdx.x;   // (b*S+s)*HV+hv
    if (i >= (size_t)B_*S_*HV_) return;
    int    hv = (int)(i % HV_);
    size_t bs = i / HV_;
    float  Ae = expf(A_log[hv]);
    float4 r;
    #pragma unroll
    for (int u = 0; u < 2; u++) {
        size_t idx = (2*bs + u) * HV_ + hv;
        float x  = a[idx] + dt_bias[hv];
        float sp = (x <= 20.0f) ? log1pf(expf(x)) : x;   // softplus
        float eg = expf(-Ae * sp);
        float bt = 1.0f / (1.0f + expf(-b[idx]));
        if (u == 0) { r.x = eg; r.y = bt; } else { r.z = eg; r.w = bt; }
    }
    g_gb4[i] = r;
}

// ---------------------------------------------------------------------------
// Main persistent recurrence, 2-step fused, smem-staged k/q.
// grid = 128 CTAs, 256 threads. Thread map unchanged from R10:
//   ko = tid&7 (16 k-rows), vg = tid>>3 (2 adjacent V cols).
// Chunk loop (16 steps): cooperatively stage k+q (16KB) into a swizzled smem
// buffer (80B octant stride -> conflict-free LDS), double-buffered so the
// staging LDGs of chunk c+1 overlap the FMA work of chunk c. One
// __syncthreads per chunk. Compute math identical to R10.
// ---------------------------------------------------------------------------
__global__ void __launch_bounds__(256, 1) gdn_recurrent(
    const float* __restrict__ vin,
    const float* __restrict__ h0src,
    const int*   __restrict__ h0idx,
    float* __restrict__ out)
{
    __shared__ __align__(16) char smem[2 * BUFB];   // 40 KB

    int blk   = blockIdx.x;
    int vhalf = blk & 1;
    int hv    = (blk >> 1) & (HV_ - 1);
    int b     = blk >> 4;
    int tid   = threadIdx.x;
    int ko    = tid & 7;          // K-octant: rows [ko*16, ko*16+16)
    int vg    = tid >> 3;         // 0..31 -> V columns vg*2, vg*2+1
    int v0    = vhalf * 64 + vg * 2;
    int hh    = hv / REP_;

    // State tile: h[i] = k-row (ko*16+i), columns (v0, v0+1)
    float2 h[16];
    int idx = h0idx[b];
    if (idx >= 0) {
        const float* src = h0src + (((size_t)idx * HV_ + hv) * K_ + (size_t)ko * 16) * V_ + v0;
        #pragma unroll
        for (int i = 0; i < 16; i++)
            h[i] = *reinterpret_cast<const float2*>(src + (size_t)i * V_);
    } else {
        #pragma unroll
        for (int i = 0; i < 16; i++) h[i] = make_float2(0.f, 0.f);
    }

    const int VSTR = HV_ * V_ / 2;      // float2 stride per t-step

    const float*  kgm = g_kn + ((size_t)b*T_*H_ + hh)*K_;   // chunk staging bases
    const float*  qgm = g_qn + ((size_t)b*T_*H_ + hh)*K_;
    const float4* ddp = g_d   + (size_t)b*S_*H_  + hh;
    const float4* gbp = g_gb4 + (size_t)b*S_*HV_ + hv;
    const float2* vp  = reinterpret_cast<const float2*>(vin + ((size_t)b*T_*HV_ + hv)*V_ + v0);
    float2*       op  = reinterpret_cast<float2*>(out + ((size_t)b*T_*HV_ + hv)*V_ + v0);

    // Per-thread staging decode: thread handles float4 indices tid + 256*r.
    // idx bits: step = idx>>6 (16 steps), strm = (idx>>5)&1 (0=k,1=q),
    //           w16 = idx&31 -> ko_s = w16>>2, j_s = w16&3.
    int s_step[4], s_soff[4], s_woff[4];
    #pragma unroll
    for (int r = 0; r < 4; r++) {
        int fidx = tid + 256 * r;
        int step = fidx >> 6;
        int strm = (fidx >> 5) & 1;
        int w16  = fidx & 31;
        s_step[r] = step;
        s_woff[r] = w16 * 4;                               // float offset in row
        s_soff[r] = step * STEPB + strm * ROWB + (w16 >> 2) * 80 + (w16 & 3) * 16;
    }

    #define STAGE(CH, BUF)                                                     \
    {                                                                          \
        const float* kb = kgm + (size_t)(CH) * CHS * (H_ * K_);                \
        const float* qb = qgm + (size_t)(CH) * CHS * (H_ * K_);                \
        char* dst = smem + (BUF) * BUFB;                                       \
        _Pragma("unroll")                                                      \
        for (int r = 0; r < 4; r++) {                                          \
            const float* srcb = ((tid + 256*r) & 32) ? qb : kb;                \
            float4 val = *reinterpret_cast<const float4*>(                     \
                srcb + (size_t)s_step[r] * (H_ * K_) + s_woff[r]);             \
            *reinterpret_cast<float4*>(dst + s_soff[r]) = val;                 \
        }                                                                      \
    }

    STAGE(0, 0);
    __syncthreads();

    int my_oct = ko * 80;

    #pragma unroll 1
    for (int c = 0; c < NCH; c++) {
        int buf = c & 1;
        if (c + 1 < NCH) STAGE(c + 1, buf ^ 1);

        const char* sb = smem + buf * BUFB;

        #pragma unroll 1
        for (int g = 0; g < CHG; g++) {
            const char* p1 = sb + (2*g    ) * STEPB + my_oct;
            const char* p2 = sb + (2*g + 1) * STEPB + my_oct;

            float4 k1[4], k2[4], q1[4], q2[4];
            #pragma unroll
            for (int j = 0; j < 4; j++) {
                k1[j] = *reinterpret_cast<const float4*>(p1 + j*16);
                q1[j] = *reinterpret_cast<const float4*>(p1 + ROWB + j*16);
                k2[j] = *reinterpret_cast<const float4*>(p2 + j*16);
                q2[j] = *reinterpret_cast<const float4*>(p2 + ROWB + j*16);
            }
            float4 dd = ddp[0];       // {k1.q1, k1.k2, k1.q2, k2.q2}
            float4 gg = gbp[0];       // {eg1, beta1, eg2, beta2}
            float2 v1 = vp[0];
            float2 v2 = vp[VSTR];

            // 4 dots vs OLD h, both columns: 8 accumulators, 16-deep chains
            float k1x=0.f,k1y=0.f,k2x=0.f,k2y=0.f,q1x=0.f,q1y=0.f,q2x=0.f,q2y=0.f;
            #pragma unroll
            for (int j = 0; j < 4; j++) {
                #pragma unroll
                for (int r = 0; r < 4; r++) {
                    float2 hr = h[4*j + r];
                    float kc1 = (r==0)?k1[j].x:(r==1)?k1[j].y:(r==2)?k1[j].z:k1[j].w;
                    float kc2 = (r==0)?k2[j].x:(r==1)?k2[j].y:(r==2)?k2[j].z:k2[j].w;
                    float qc1 = (r==0)?q1[j].x:(r==1)?q1[j].y:(r==2)?q1[j].z:q1[j].w;
                    float qc2 = (r==0)?q2[j].x:(r==1)?q2[j].y:(r==2)?q2[j].z:q2[j].w;
                    k1x = fmaf(hr.x, kc1, k1x);  k1y = fmaf(hr.y, kc1, k1y);
                    k2x = fmaf(hr.x, kc2, k2x);  k2y = fmaf(hr.y, kc2, k2y);
                    q1x = fmaf(hr.x, qc1, q1x);  q1y = fmaf(hr.y, qc1, q1y);
                    q2x = fmaf(hr.x, qc2, q2x);  q2y = fmaf(hr.y, qc2, q2y);
                }
            }

            // Batched reduce over the 8 K-octants (lane bits 0..2)
            #pragma unroll
            for (int m = 1; m <= 4; m <<= 1) {
                k1x += __shfl_xor_sync(0xffffffffu, k1x, m);
                k1y += __shfl_xor_sync(0xffffffffu, k1y, m);
                k2x += __shfl_xor_sync(0xffffffffu, k2x, m);
                k2y += __shfl_xor_sync(0xffffffffu, k2y, m);
                q1x += __shfl_xor_sync(0xffffffffu, q1x, m);
                q1y += __shfl_xor_sync(0xffffffffu, q1y, m);
                q2x += __shfl_xor_sync(0xffffffffu, q2x, m);
                q2y += __shfl_xor_sync(0xffffffffu, q2y, m);
            }

            float eg1 = gg.x, b1 = gg.y, eg2 = gg.z, b2 = gg.w;
            // Step 1 scalars
            float u1x = fmaf(-eg1, k1x, v1.x) * b1;
            float u1y = fmaf(-eg1, k1y, v1.y) * b1;
            // Bridge: h1.k2 = eg1*(h.k2) + u1*(k1.k2)
            float hk2x = fmaf(u1x, dd.y, eg1 * k2x);
            float hk2y = fmaf(u1y, dd.y, eg1 * k2y);
            // Step 2 scalars
            float u2x = fmaf(-eg2, hk2x, v2.x) * b2;
            float u2y = fmaf(-eg2, hk2y, v2.y) * b2;

            if (ko == 0) {
                float2 o1, o2;
                o1.x = fmaf(eg1, q1x, u1x * dd.x);
                o1.y = fmaf(eg1, q1y, u1y * dd.x);
                float hq2x = fmaf(u1x, dd.z, eg1 * q2x);
                float hq2y = fmaf(u1y, dd.z, eg1 * q2y);
                o2.x = fmaf(eg2, hq2x, u2x * dd.w);
                o2.y = fmaf(eg2, hq2y, u2y * dd.w);
                op[0]    = o1;
                op[VSTR] = o2;
            }

            // Fused update: h = (eg1*eg2)h + (eg2*u1)k1 + u2*k2
            float e12 = eg1 * eg2;
            float c1x = eg2 * u1x, c1y = eg2 * u1y;
            #pragma unroll
            for (int j = 0; j < 4; j++) {
                #pragma unroll
                for (int r = 0; r < 4; r++) {
                    float kc1 = (r==0)?k1[j].x:(r==1)?k1[j].y:(r==2)?k1[j].z:k1[j].w;
                    float kc2 = (r==0)?k2[j].x:(r==1)?k2[j].y:(r==2)?k2[j].z:k2[j].w;
                    float2 hr = h[4*j + r];
                    hr.x = fmaf(kc2, u2x, fmaf(kc1, c1x, e12 * hr.x));
                    hr.y = fmaf(kc2, u2y, fmaf(kc1, c1y, e12 * hr.y));
                    h[4*j + r] = hr;
                }
            }

            ddp += H_;
            gbp += HV_;
            vp  += 2 * VSTR;
            op  += 2 * VSTR;
        }

        __syncthreads();   // staging c+1 complete; compute c done before c+2 overwrites
    }
    #undef STAGE
}

// ---------------------------------------------------------------------------
// Inputs (metadata order): A_log, a, dt_bias, q, k, v, b,
//                          initial_state_source, initial_state_indices
// Output: float32 [B,T,HV,V]
// ---------------------------------------------------------------------------
extern "C" void kernel_launch(void* const* d_in, const int* in_sizes, int n_in,
                              void* d_out, int out_size) {
    const float* A_log = (const float*)d_in[0];
    const float* a     = (const float*)d_in[1];
    const float* dtb   = (const float*)d_in[2];
    const float* q     = (const float*)d_in[3];
    const float* k     = (const float*)d_in[4];
    const float* v     = (const float*)d_in[5];
    const float* bb    = (const float*)d_in[6];
    const float* h0    = (const float*)d_in[7];
    const int*   h0i   = (const int*)d_in[8];
    float* out = (float*)d_out;

    prep_qk<<<(B_ * T_ * H_) / 4, 128>>>(q, k);
    prep_dots<<<(B_ * S_ * H_) / 4, 128>>>();
    prep_gate4<<<((size_t)B_ * S_ * HV_ + 255) / 256, 256>>>(A_log, a, dtb, bb);
    gdn_recurrent<<<B_ * HV_ * 2, 256>>>(v, h0, h0i, out);
}